// round 8
// baseline (speedup 1.0000x reference)
#include <cuda_runtime.h>
#include <cuda_bf16.h>
#include <cstdint>
#include <math.h>

// ---------------------------------------------------------------------------
// Problem constants
// ---------------------------------------------------------------------------
#define BATCH      4
#define SEQ        1024
#define DEMB       8192
#define NHEAD      8
#define DKV        256
#define QKVDIM     (NHEAD * DKV)          // 2048
#define TOK_TOTAL  (BATCH * SEQ)          // 4096
#define PLANE      ((long)SEQ * DEMB)

// ---------------------------------------------------------------------------
// Scratch (static device allocations — no cudaMalloc allowed)
// ---------------------------------------------------------------------------
__device__ __align__(256) float  g_X[(long)BATCH * SEQ * DEMB];
__device__ __align__(256) float  g_V[(long)BATCH * SEQ * QKVDIM];
__device__ __align__(256) float  g_S[(long)BATCH * NHEAD * SEQ * SEQ];
__device__ __align__(256) float  g_O[(long)BATCH * SEQ * DEMB];
__device__ double g_part[BATCH * 1024 * 2];
__device__ double g_mean[BATCH];
__device__ double g_rstd[BATCH];

__device__ __align__(256) __nv_bfloat16 g_Xh[(long)BATCH * SEQ * DEMB];
__device__ __align__(256) __nv_bfloat16 g_Xl[(long)BATCH * SEQ * DEMB];
__device__ __align__(256) __nv_bfloat16 g_Wqkvth[(long)3 * QKVDIM * DEMB];
__device__ __align__(256) __nv_bfloat16 g_Wqkvtl[(long)3 * QKVDIM * DEMB];
__device__ __align__(256) __nv_bfloat16 g_Woth[(long)DEMB * QKVDIM];
__device__ __align__(256) __nv_bfloat16 g_Wotl[(long)DEMB * QKVDIM];
__device__ __align__(256) __nv_bfloat16 g_Qh[(long)BATCH * SEQ * QKVDIM];
__device__ __align__(256) __nv_bfloat16 g_Ql[(long)BATCH * SEQ * QKVDIM];
__device__ __align__(256) __nv_bfloat16 g_Kh[(long)BATCH * SEQ * QKVDIM];
__device__ __align__(256) __nv_bfloat16 g_Kl[(long)BATCH * SEQ * QKVDIM];
__device__ __align__(256) __nv_bfloat16 g_Vth[(long)BATCH * NHEAD * DKV * SEQ];
__device__ __align__(256) __nv_bfloat16 g_Vtl[(long)BATCH * NHEAD * DKV * SEQ];
__device__ __align__(256) __nv_bfloat16 g_Ph[(long)BATCH * NHEAD * SEQ * SEQ];
__device__ __align__(256) __nv_bfloat16 g_Pl[(long)BATCH * NHEAD * SEQ * SEQ];
__device__ __align__(256) __nv_bfloat16 g_Zh[(long)BATCH * SEQ * QKVDIM];
__device__ __align__(256) __nv_bfloat16 g_Zl[(long)BATCH * SEQ * QKVDIM];

// ---------------------------------------------------------------------------
// PTX helpers
// ---------------------------------------------------------------------------
__device__ __forceinline__ uint32_t smem_u32(const void* p) {
    uint32_t a;
    asm("{ .reg .u64 t; cvta.to.shared.u64 t, %1; cvt.u32.u64 %0, t; }"
        : "=r"(a) : "l"(p));
    return a;
}
__device__ __forceinline__ void cpasync16(uint32_t dst, const void* src) {
    asm volatile("cp.async.cg.shared.global [%0], [%1], 16;" :: "r"(dst), "l"(src));
}
__device__ __forceinline__ void cp_commit() {
    asm volatile("cp.async.commit_group;" ::: "memory");
}
template <int N> __device__ __forceinline__ void cp_wait() {
    asm volatile("cp.async.wait_group %0;" :: "n"(N) : "memory");
}
__device__ __forceinline__ void ldsm4(uint32_t* r, uint32_t addr) {
    asm volatile("ldmatrix.sync.aligned.m8n8.x4.shared.b16 {%0,%1,%2,%3}, [%4];"
                 : "=r"(r[0]), "=r"(r[1]), "=r"(r[2]), "=r"(r[3]) : "r"(addr));
}
__device__ __forceinline__ void mma16816(float* c, const uint32_t* a, const uint32_t* b) {
    asm volatile(
        "mma.sync.aligned.m16n8k16.row.col.f32.bf16.bf16.f32 "
        "{%0,%1,%2,%3}, {%4,%5,%6,%7}, {%8,%9}, {%0,%1,%2,%3};"
        : "+f"(c[0]), "+f"(c[1]), "+f"(c[2]), "+f"(c[3])
        : "r"(a[0]), "r"(a[1]), "r"(a[2]), "r"(a[3]), "r"(b[0]), "r"(b[1]));
}
__device__ __forceinline__ __nv_bfloat162 split_hi2(float x, float y) {
    __nv_bfloat162 h;
    h.x = __float2bfloat16(x); h.y = __float2bfloat16(y);
    return h;
}
__device__ __forceinline__ __nv_bfloat162 split_lo2(float x, float y, __nv_bfloat162 h) {
    __nv_bfloat162 l;
    l.x = __float2bfloat16(x - __bfloat162float(h.x));
    l.y = __float2bfloat16(y - __bfloat162float(h.y));
    return l;
}

// ---------------------------------------------------------------------------
// Split-precision bf16 GEMM on mma.sync.
// acc = alpha * (Ah*Bh^T + Ah*Bl^T + Al*Bh^T) (+ D), fp32 accum in regs.
// Tile 128(M) x 256(N), KC=32, 3-stage cp.async pipeline.
// Smem rows padded to 80B (64B data + 16B pad) -> conflict-free ldsm, no XOR.
// mode 0: outputs Cf (fp32) and/or Ch/Cl (bf16 hi/lo).
// mode 1 (fused QKV): column segment seg=col0>>11 routes to
//         seg0 -> Ch/Cl (Q), seg1 -> C2h/C2l (K), seg2 -> Cf (V fp32); ldc=2048.
// Batch z: offset = (z/inner)*so + (z%inner)*si per operand.
// ---------------------------------------------------------------------------
#define KC       32
#define ROW_B    80                        // padded row bytes (64 data + 16 pad)
#define A_TILE   (128 * ROW_B)             // 10240
#define B_TILE   (256 * ROW_B)             // 20480
#define OFF_AH   0
#define OFF_AL   A_TILE
#define OFF_BH   (2 * A_TILE)
#define OFF_BL   (2 * A_TILE + B_TILE)
#define STAGE_B  (2 * A_TILE + 2 * B_TILE) // 61440
#define NSTAGE   3
#define SMEM_DYN (NSTAGE * STAGE_B)        // 184320

__global__ __launch_bounds__(256, 1)
void mma_gemm(const __nv_bfloat16* __restrict__ Ah, const __nv_bfloat16* __restrict__ Al,
              int lda, long sAo, long sAi,
              const __nv_bfloat16* __restrict__ Bh, const __nv_bfloat16* __restrict__ Bl,
              int ldb, long sBo, long sBi,
              float* __restrict__ Cf,
              __nv_bfloat16* __restrict__ Ch, __nv_bfloat16* __restrict__ Cl,
              __nv_bfloat16* __restrict__ C2h, __nv_bfloat16* __restrict__ C2l,
              int ldc, long sCo, long sCi,
              const float* __restrict__ D,
              int K, int inner, float alpha, int mode)
{
    extern __shared__ __align__(128) char dsm_raw[];
    const uint32_t dsm0 = smem_u32(dsm_raw);

    const int tid  = threadIdx.x;
    const int lane = tid & 31;
    const int wid  = tid >> 5;
    const int wm   = wid & 1;             // warp row (2): 64 rows each
    const int wn   = wid >> 1;            // warp col (4): 64 cols each

    const int z  = blockIdx.z;
    const int zo = z / inner, zi = z - zo * inner;
    Ah += zo * sAo + zi * sAi;  Al += zo * sAo + zi * sAi;
    Bh += zo * sBo + zi * sBi;  Bl += zo * sBo + zi * sBi;
    const long coff = zo * sCo + zi * sCi;

    // grouped rasterization: 8 M-tiles per stripe
    int pid_m, pid_n;
    {
        const int ntm = gridDim.y, ntn = gridDim.x;
        const int lin = blockIdx.y * ntn + blockIdx.x;
        const int G = 8;
        const int width = G * ntn;
        const int grp = lin / width;
        const int rem = lin - grp * width;
        const int m0  = grp * G;
        const int gsz = (ntm - m0 < G) ? (ntm - m0) : G;
        pid_m = m0 + rem % gsz;
        pid_n = rem / gsz;
    }
    const int row0 = pid_m * 128;
    const int col0 = pid_n * 256;

    // cp.async geometry: per thread, A: 2 chunks each for hi/lo, B: 4 each
    const int aR = tid >> 2;              // 0..63 base row
    const int aC = tid & 3;               // 16B chunk in row
    const uint32_t cOff = (uint32_t)(aC * 16);
    const int gC = aC * 8;                // bf16 col offset in K-chunk

    const int nk = K / KC;

    auto load_stage = [&](int s, int k0) {
        const uint32_t sb = dsm0 + s * STAGE_B;
        #pragma unroll
        for (int j = 0; j < 2; j++) {
            const int r = aR + 64 * j;
            const uint32_t so = (uint32_t)(r * ROW_B) + cOff;
            const long go = (long)(row0 + r) * lda + k0 + gC;
            cpasync16(sb + OFF_AH + so, Ah + go);
            cpasync16(sb + OFF_AL + so, Al + go);
        }
        #pragma unroll
        for (int j = 0; j < 4; j++) {
            const int r = aR + 64 * j;
            const uint32_t so = (uint32_t)(r * ROW_B) + cOff;
            const long go = (long)(col0 + r) * ldb + k0 + gC;
            cpasync16(sb + OFF_BH + so, Bh + go);
            cpasync16(sb + OFF_BL + so, Bl + go);
        }
        cp_commit();
    };

    // ldsm lane geometry (validated pattern from round-5 kernel)
    const int l7   = lane & 7;
    const uint32_t aLd = (uint32_t)((wm * 64 + l7 + ((lane >> 3) & 1) * 8) * ROW_B
                                    + ((lane >> 4) & 1) * 16);
    const uint32_t bLd = (uint32_t)((wn * 64 + ((lane >> 4) & 1) * 8 + l7) * ROW_B
                                    + ((lane >> 3) & 1) * 16);

    float acc[4][8][4];
    #pragma unroll
    for (int mt = 0; mt < 4; mt++)
        #pragma unroll
        for (int nt = 0; nt < 8; nt++)
            #pragma unroll
            for (int q = 0; q < 4; q++) acc[mt][nt][q] = 0.f;

    load_stage(0, 0);
    load_stage(1, KC);

    for (int i = 0; i < nk; ++i) {
        const int s = i % NSTAGE;
        if (i + 1 < nk) cp_wait<1>(); else cp_wait<0>();
        __syncthreads();
        if (i + 2 < nk) load_stage((i + 2) % NSTAGE, (i + 2) * KC);

        const uint32_t sb = dsm0 + s * STAGE_B;
        #pragma unroll
        for (int ks = 0; ks < 2; ++ks) {
            uint32_t ah[4][4], al[4][4], bh[8][2], bl[8][2];
            const uint32_t kOff = (uint32_t)(ks * 32);
            #pragma unroll
            for (int mt = 0; mt < 4; mt++) {
                const uint32_t ad = sb + aLd + mt * (16 * ROW_B) + kOff;
                ldsm4(ah[mt], ad + OFF_AH);
                ldsm4(al[mt], ad + OFF_AL);
            }
            #pragma unroll
            for (int p = 0; p < 4; p++) {   // nt pairs
                const uint32_t bd = sb + bLd + p * (16 * ROW_B) + kOff;
                ldsm4(&bh[2 * p][0], bd + OFF_BH);
                ldsm4(&bl[2 * p][0], bd + OFF_BL);
            }
            #pragma unroll
            for (int mt = 0; mt < 4; mt++)
                #pragma unroll
                for (int nt = 0; nt < 8; nt++) {
                    mma16816(acc[mt][nt], ah[mt], bh[nt]);
                    mma16816(acc[mt][nt], ah[mt], bl[nt]);
                    mma16816(acc[mt][nt], al[mt], bh[nt]);
                }
        }
        // no bottom barrier: next iteration's top barrier protects stage reuse
    }

    // ---- epilogue
    float* cf = Cf;
    __nv_bfloat16 *ch = Ch, *cl = Cl;
    int cbase = col0;
    if (mode) {
        const int seg = col0 >> 11;
        cbase = col0 & 2047;
        if (seg == 0)      { cf = nullptr; ch = Ch;  cl = Cl;  }
        else if (seg == 1) { cf = nullptr; ch = C2h; cl = C2l; }
        else               { ch = nullptr; cl = nullptr; }
    }
    if (cf) cf += coff;
    if (ch) { ch += coff; cl += coff; }
    const float* dp = D ? (D + coff) : (const float*)0;

    const int cg = lane >> 2, tg = lane & 3;
    #pragma unroll
    for (int mt = 0; mt < 4; mt++) {
        #pragma unroll
        for (int nt = 0; nt < 8; nt++) {
            const int r = row0 + wm * 64 + mt * 16 + cg;
            const int c = cbase + wn * 64 + nt * 8 + tg * 2;
            const long o0 = (long)r * ldc + c;
            const long o1 = (long)(r + 8) * ldc + c;
            float2 v0, v1;
            v0.x = acc[mt][nt][0] * alpha; v0.y = acc[mt][nt][1] * alpha;
            v1.x = acc[mt][nt][2] * alpha; v1.y = acc[mt][nt][3] * alpha;
            if (dp) {
                float2 d0 = *(const float2*)(dp + o0);
                float2 d1 = *(const float2*)(dp + o1);
                v0.x += d0.x; v0.y += d0.y; v1.x += d1.x; v1.y += d1.y;
            }
            if (cf) {
                *(float2*)(cf + o0) = v0;
                *(float2*)(cf + o1) = v1;
            }
            if (ch) {
                __nv_bfloat162 h0 = split_hi2(v0.x, v0.y);
                __nv_bfloat162 h1 = split_hi2(v1.x, v1.y);
                *(__nv_bfloat162*)(ch + o0) = h0;
                *(__nv_bfloat162*)(ch + o1) = h1;
                *(__nv_bfloat162*)(cl + o0) = split_lo2(v0.x, v0.y, h0);
                *(__nv_bfloat162*)(cl + o1) = split_lo2(v1.x, v1.y, h1);
            }
        }
    }
}

// ---------------------------------------------------------------------------
// fp32 [R,C] -> bf16 hi/lo transposed [C,R]  (batched via strides)
// Vectorized write phase: bf162 stores, conflict-free smem reads.
// ---------------------------------------------------------------------------
__global__ void tsplit_kernel(const float* __restrict__ in, long sIo, long sIi, int ldin,
                              __nv_bfloat16* __restrict__ hi, __nv_bfloat16* __restrict__ lo,
                              long sOo, long sOi, int ldo, int inner)
{
    __shared__ float tile[32][33];
    const int z = blockIdx.z, zo = z / inner, zi = z - zo * inner;
    in += zo * sIo + zi * sIi;
    hi += zo * sOo + zi * sOi;
    lo += zo * sOo + zi * sOi;
    const int r0 = blockIdx.y * 32, c0 = blockIdx.x * 32;
    const int tx = threadIdx.x, ty = threadIdx.y;
    #pragma unroll
    for (int i = 0; i < 4; i++)
        tile[ty + i * 8][tx] = in[(long)(r0 + ty + i * 8) * ldin + c0 + tx];
    __syncthreads();
    const int t  = ty * 32 + tx;
    const int rp = t & 15;          // row pair
    const int cb = t >> 4;          // 0..15
    #pragma unroll
    for (int pass = 0; pass < 2; pass++) {
        const int cl_ = cb + pass * 16;
        const float v0 = tile[2 * rp][cl_];
        const float v1 = tile[2 * rp + 1][cl_];
        __nv_bfloat162 h = split_hi2(v0, v1);
        const long o = (long)(c0 + cl_) * ldo + r0 + 2 * rp;
        *(__nv_bfloat162*)(hi + o) = h;
        *(__nv_bfloat162*)(lo + o) = split_lo2(v0, v1, h);
    }
}

// ---------------------------------------------------------------------------
// build X (gather + transpose + PE) writing fp32 AND bf16 hi/lo
// ---------------------------------------------------------------------------
__global__ void build_x_kernel(const float* __restrict__ ref,
                               const float* __restrict__ hd,
                               float* __restrict__ X,
                               __nv_bfloat16* __restrict__ Xh,
                               __nv_bfloat16* __restrict__ Xl)
{
    __shared__ float tile[32][33];
    const int b  = blockIdx.z;
    const int f0 = blockIdx.x * 32;
    const int t0 = blockIdx.y * 32;
    const int tx = threadIdx.x, ty = threadIdx.y;

#pragma unroll
    for (int i = 0; i < 4; i++) {
        int f  = f0 + ty + i * 8;
        int n_ = f >> 10;
        int s  = f & 1023;
        int hh = s >> 5;
        int ww = s & 31;
        const float* src = (ww < 16)
            ? ref + ((long)(((b * 8 + n_) * 32 + hh) * 16 + ww)) * 1024
            : hd  + ((long)(((b * 8 + n_) * 32 + hh) * 16 + (ww - 16))) * 1024;
        tile[ty + i * 8][tx] = src[t0 + tx];
    }
    __syncthreads();
#pragma unroll
    for (int i = 0; i < 4; i++) {
        int t = t0 + ty + i * 8;
        int f = f0 + tx;
        float freq = __expf((float)f * (-9.210340371976184f / 4096.0f));
        float ang  = (float)t * freq;
        float pe   = (f & 1) ? cosf(ang) : sinf(ang);
        float v    = tile[tx][ty + i * 8] + 0.001f * pe;
        long  o    = (long)b * PLANE + (long)t * DEMB + f;
        X[o] = v;
        __nv_bfloat16 h = __float2bfloat16(v);
        Xh[o] = h;
        Xl[o] = __float2bfloat16(v - __bfloat162float(h));
    }
}

// ---------------------------------------------------------------------------
// Softmax over rows of S, writing bf16 hi/lo P directly.
// ---------------------------------------------------------------------------
__global__ void softmax_kernel(const float* __restrict__ S,
                               __nv_bfloat16* __restrict__ Ph,
                               __nv_bfloat16* __restrict__ Pl)
{
    __shared__ float red[8];
    const int tid  = threadIdx.x;
    const int lane = tid & 31, warp = tid >> 5;
    const float4* row = (const float4*)(S + (long)blockIdx.x * SEQ);
    float4 v = row[tid];

    float m = fmaxf(fmaxf(v.x, v.y), fmaxf(v.z, v.w));
#pragma unroll
    for (int o = 16; o; o >>= 1) m = fmaxf(m, __shfl_xor_sync(~0u, m, o));
    if (lane == 0) red[warp] = m;
    __syncthreads();
    float M = red[0];
#pragma unroll
    for (int i = 1; i < 8; i++) M = fmaxf(M, red[i]);

    v.x = __expf(v.x - M); v.y = __expf(v.y - M);
    v.z = __expf(v.z - M); v.w = __expf(v.w - M);
    float s = v.x + v.y + v.z + v.w;
#pragma unroll
    for (int o = 16; o; o >>= 1) s += __shfl_xor_sync(~0u, s, o);
    __syncthreads();
    if (lane == 0) red[warp] = s;
    __syncthreads();
    float T = 0.f;
#pragma unroll
    for (int i = 0; i < 8; i++) T += red[i];
    float inv = 1.0f / T;
    v.x *= inv; v.y *= inv; v.z *= inv; v.w *= inv;

    const long o = (long)blockIdx.x * SEQ + tid * 4;
    __nv_bfloat162 h0 = split_hi2(v.x, v.y);
    __nv_bfloat162 h1 = split_hi2(v.z, v.w);
    *(__nv_bfloat162*)(Ph + o)     = h0;
    *(__nv_bfloat162*)(Ph + o + 2) = h1;
    *(__nv_bfloat162*)(Pl + o)     = split_lo2(v.x, v.y, h0);
    *(__nv_bfloat162*)(Pl + o + 2) = split_lo2(v.z, v.w, h1);
}

// ---------------------------------------------------------------------------
// LayerNorm statistics + output
// ---------------------------------------------------------------------------
__global__ void reduce_partial_kernel(const float* __restrict__ O,
                                      double* __restrict__ part)
{
    __shared__ double sh[256], sh2[256];
    const int b   = blockIdx.y;
    const int tid = threadIdx.x;
    const float* p = O + (long)b * PLANE;
    const int base = blockIdx.x * 256 + tid;
    double s = 0.0, s2 = 0.0;
#pragma unroll
    for (int i = 0; i < 32; i++) {
        float v = p[base + i * 262144];
        s  += v;
        s2 += (double)v * v;
    }
    sh[tid] = s; sh2[tid] = s2;
    __syncthreads();
    for (int o = 128; o; o >>= 1) {
        if (tid < o) { sh[tid] += sh[tid + o]; sh2[tid] += sh2[tid + o]; }
        __syncthreads();
    }
    if (tid == 0) {
        part[(b * 1024 + blockIdx.x) * 2 + 0] = sh[0];
        part[(b * 1024 + blockIdx.x) * 2 + 1] = sh2[0];
    }
}

__global__ void finalize_stats_kernel(const double* __restrict__ part)
{
    __shared__ double sh[256], sh2[256];
    const int b = blockIdx.x, tid = threadIdx.x;
    double s = 0.0, s2 = 0.0;
    for (int i = tid; i < 1024; i += 256) {
        s  += part[(b * 1024 + i) * 2 + 0];
        s2 += part[(b * 1024 + i) * 2 + 1];
    }
    sh[tid] = s; sh2[tid] = s2;
    __syncthreads();
    for (int o = 128; o; o >>= 1) {
        if (tid < o) { sh[tid] += sh[tid + o]; sh2[tid] += sh2[tid + o]; }
        __syncthreads();
    }
    if (tid == 0) {
        double n    = (double)PLANE;
        double mean = sh[0] / n;
        double var  = sh2[0] / n - mean * mean;
        g_mean[b] = mean;
        g_rstd[b] = rsqrt(var + 1e-6);
    }
}

__global__ void ln_out_kernel(const float* __restrict__ O,
                              const float* __restrict__ gamma,
                              const float* __restrict__ beta,
                              float* __restrict__ out)
{
    __shared__ float tile[32][33];
    const int bz = blockIdx.z;
    const int b  = bz >> 3;
    const int nf = (bz & 7) * 1024;
    const int c0 = blockIdx.x * 32;
    const int t0 = blockIdx.y * 32;
    const int tx = threadIdx.x, ty = threadIdx.y;
    const float mean = (float)g_mean[b];
    const float rstd = (float)g_rstd[b];

#pragma unroll
    for (int i = 0; i < 4; i++) {
        int t   = t0 + ty + i * 8;
        long fi = (long)t * DEMB + nf + c0 + tx;
        float v = O[(long)b * PLANE + fi];
        tile[ty + i * 8][tx] = (v - mean) * rstd * gamma[fi] + beta[fi];
    }
    __syncthreads();
#pragma unroll
    for (int i = 0; i < 4; i++) {
        int c = c0 + ty + i * 8;
        out[((long)bz * 1024 + c) * 1024 + t0 + tx] = tile[tx][ty + i * 8];
    }
}

// ---------------------------------------------------------------------------
// Launcher
// ---------------------------------------------------------------------------
extern "C" void kernel_launch(void* const* d_in, const int* in_sizes, int n_in,
                              void* d_out, int out_size)
{
    const float* ref_img = (const float*)d_in[0];
    const float* hdmap   = (const float*)d_in[1];
    const float* w_q     = (const float*)d_in[2];
    const float* w_k     = (const float*)d_in[3];
    const float* w_v     = (const float*)d_in[4];
    const float* w_o     = (const float*)d_in[5];
    const float* gamma   = (const float*)d_in[6];
    const float* beta    = (const float*)d_in[7];
    float* out = (float*)d_out;

    float *X, *V, *S, *O;  double* part;
    __nv_bfloat16 *Xh, *Xl, *Wqkvth, *Wqkvtl, *Woth, *Wotl;
    __nv_bfloat16 *Qh, *Ql, *Kh, *Kl, *Vth, *Vtl, *Ph, *Pl, *Zh, *Zl;
    cudaGetSymbolAddress((void**)&X, g_X);     cudaGetSymbolAddress((void**)&V, g_V);
    cudaGetSymbolAddress((void**)&S, g_S);     cudaGetSymbolAddress((void**)&O, g_O);
    cudaGetSymbolAddress((void**)&part, g_part);
    cudaGetSymbolAddress((void**)&Xh, g_Xh);   cudaGetSymbolAddress((void**)&Xl, g_Xl);
    cudaGetSymbolAddress((void**)&Wqkvth, g_Wqkvth);
    cudaGetSymbolAddress((void**)&Wqkvtl, g_Wqkvtl);
    cudaGetSymbolAddress((void**)&Woth, g_Woth); cudaGetSymbolAddress((void**)&Wotl, g_Wotl);
    cudaGetSymbolAddress((void**)&Qh, g_Qh);   cudaGetSymbolAddress((void**)&Ql, g_Ql);
    cudaGetSymbolAddress((void**)&Kh, g_Kh);   cudaGetSymbolAddress((void**)&Kl, g_Kl);
    cudaGetSymbolAddress((void**)&Vth, g_Vth); cudaGetSymbolAddress((void**)&Vtl, g_Vtl);
    cudaGetSymbolAddress((void**)&Ph, g_Ph);   cudaGetSymbolAddress((void**)&Pl, g_Pl);
    cudaGetSymbolAddress((void**)&Zh, g_Zh);   cudaGetSymbolAddress((void**)&Zl, g_Zl);

    cudaFuncSetAttribute(mma_gemm, cudaFuncAttributeMaxDynamicSharedMemorySize, SMEM_DYN);

    const dim3 tb32x8(32, 8);

    // 1) build X (gather + transpose + PE) with fused hi/lo split
    build_x_kernel<<<dim3(DEMB / 32, SEQ / 32, BATCH), tb32x8>>>(ref_img, hdmap, X, Xh, Xl);

    // 2) weight transpose + split: w_q/k/v -> rows of Wqkvt [6144, 8192]; w_o -> Wot
    tsplit_kernel<<<dim3(QKVDIM / 32, DEMB / 32, 1), tb32x8>>>(
        w_q, 0, 0, QKVDIM, Wqkvth, Wqkvtl, 0, 0, DEMB, 1);
    tsplit_kernel<<<dim3(QKVDIM / 32, DEMB / 32, 1), tb32x8>>>(
        w_k, 0, 0, QKVDIM, Wqkvth + (long)QKVDIM * DEMB, Wqkvtl + (long)QKVDIM * DEMB, 0, 0, DEMB, 1);
    tsplit_kernel<<<dim3(QKVDIM / 32, DEMB / 32, 1), tb32x8>>>(
        w_v, 0, 0, QKVDIM, Wqkvth + (long)2 * QKVDIM * DEMB, Wqkvtl + (long)2 * QKVDIM * DEMB, 0, 0, DEMB, 1);
    tsplit_kernel<<<dim3(DEMB / 32, QKVDIM / 32, 1), tb32x8>>>(
        w_o, 0, 0, DEMB, Woth, Wotl, 0, 0, QKVDIM, 1);

    // 3) fused QKV projection: [4096,8192] x [8192,6144], epilogue routes
    mma_gemm<<<dim3(3 * QKVDIM / 256, TOK_TOTAL / 128, 1), 256, SMEM_DYN>>>(
        Xh, Xl, DEMB, 0, 0,
        Wqkvth, Wqkvtl, DEMB, 0, 0,
        V, Qh, Ql, Kh, Kl, QKVDIM, 0, 0,
        nullptr, DEMB, 1, 1.0f, 1);

    // 4) transpose+split V per head -> Vt[b,h,d,t]
    tsplit_kernel<<<dim3(DKV / 32, SEQ / 32, BATCH * NHEAD), tb32x8>>>(
        V, (long)SEQ * QKVDIM, DKV, QKVDIM,
        Vth, Vtl, (long)NHEAD * DKV * SEQ, (long)DKV * SEQ, SEQ, NHEAD);

    // 5) scores S = (1/16) Q K^T per (b,h)
    const long sQKo = (long)SEQ * QKVDIM;
    const long sSo  = (long)NHEAD * SEQ * SEQ;
    mma_gemm<<<dim3(SEQ / 256, SEQ / 128, BATCH * NHEAD), 256, SMEM_DYN>>>(
        Qh, Ql, QKVDIM, sQKo, DKV,
        Kh, Kl, QKVDIM, sQKo, DKV,
        S, nullptr, nullptr, nullptr, nullptr, SEQ, sSo, (long)SEQ * SEQ,
        nullptr, DKV, NHEAD, 0.0625f, 0);

    // 6) softmax with fused P split
    softmax_kernel<<<BATCH * NHEAD * SEQ, 256>>>(S, Ph, Pl);

    // 7) Z = P @ V per (b,h), writes Zh/Zl
    mma_gemm<<<dim3(DKV / 256, SEQ / 128, BATCH * NHEAD), 256, SMEM_DYN>>>(
        Ph, Pl, SEQ, sSo, (long)SEQ * SEQ,
        Vth, Vtl, SEQ, (long)NHEAD * DKV * SEQ, (long)DKV * SEQ,
        nullptr, Zh, Zl, nullptr, nullptr, QKVDIM, sQKo, DKV,
        nullptr, SEQ, NHEAD, 1.0f, 0);

    // 8) O = Z @ w_o + X (residual)
    mma_gemm<<<dim3(DEMB / 256, TOK_TOTAL / 128, 1), 256, SMEM_DYN>>>(
        Zh, Zl, QKVDIM, 0, 0, Woth, Wotl, QKVDIM, 0, 0,
        O, nullptr, nullptr, nullptr, nullptr, DEMB, 0, 0,
        X, QKVDIM, 1, 1.0f, 0);

    // 9) LayerNorm stats + normalize/transpose out
    reduce_partial_kernel<<<dim3(1024, BATCH), 256>>>(O, part);
    finalize_stats_kernel<<<BATCH, 256>>>(part);
    ln_out_kernel<<<dim3(32, 32, BATCH * NHEAD), tb32x8>>>(O, gamma, beta, out);
}

// round 9
// speedup vs baseline: 1.1092x; 1.1092x over previous
#include <cuda_runtime.h>
#include <cuda_bf16.h>
#include <cstdint>
#include <math.h>

// ---------------------------------------------------------------------------
// Problem constants
// ---------------------------------------------------------------------------
#define BATCH      4
#define SEQ        1024
#define DEMB       8192
#define NHEAD      8
#define DKV        256
#define QKVDIM     (NHEAD * DKV)          // 2048
#define TOK_TOTAL  (BATCH * SEQ)          // 4096
#define PLANE      ((long)SEQ * DEMB)

// ---------------------------------------------------------------------------
// Scratch (static device allocations — no cudaMalloc allowed)
// ---------------------------------------------------------------------------
__device__ __align__(256) float  g_X[(long)BATCH * SEQ * DEMB];
__device__ __align__(256) float  g_V[(long)BATCH * SEQ * QKVDIM];
__device__ __align__(256) float  g_S[(long)BATCH * NHEAD * SEQ * SEQ];
__device__ __align__(256) float  g_O[(long)BATCH * SEQ * DEMB];
__device__ double g_part[BATCH * 1024 * 2];
__device__ double g_mean[BATCH];
__device__ double g_rstd[BATCH];

__device__ __align__(256) __nv_bfloat16 g_Xh[(long)BATCH * SEQ * DEMB];
__device__ __align__(256) __nv_bfloat16 g_Xl[(long)BATCH * SEQ * DEMB];
__device__ __align__(256) __nv_bfloat16 g_Wqkvth[(long)3 * QKVDIM * DEMB];
__device__ __align__(256) __nv_bfloat16 g_Wqkvtl[(long)3 * QKVDIM * DEMB];
__device__ __align__(256) __nv_bfloat16 g_Woth[(long)DEMB * QKVDIM];
__device__ __align__(256) __nv_bfloat16 g_Wotl[(long)DEMB * QKVDIM];
__device__ __align__(256) __nv_bfloat16 g_Qh[(long)BATCH * SEQ * QKVDIM];
__device__ __align__(256) __nv_bfloat16 g_Ql[(long)BATCH * SEQ * QKVDIM];
__device__ __align__(256) __nv_bfloat16 g_Kh[(long)BATCH * SEQ * QKVDIM];
__device__ __align__(256) __nv_bfloat16 g_Kl[(long)BATCH * SEQ * QKVDIM];
__device__ __align__(256) __nv_bfloat16 g_Vth[(long)BATCH * NHEAD * DKV * SEQ];
__device__ __align__(256) __nv_bfloat16 g_Vtl[(long)BATCH * NHEAD * DKV * SEQ];
__device__ __align__(256) __nv_bfloat16 g_Ph[(long)BATCH * NHEAD * SEQ * SEQ];
__device__ __align__(256) __nv_bfloat16 g_Pl[(long)BATCH * NHEAD * SEQ * SEQ];
__device__ __align__(256) __nv_bfloat16 g_Zh[(long)BATCH * SEQ * QKVDIM];
__device__ __align__(256) __nv_bfloat16 g_Zl[(long)BATCH * SEQ * QKVDIM];

// ---------------------------------------------------------------------------
// PTX helpers
// ---------------------------------------------------------------------------
__device__ __forceinline__ uint32_t smem_u32(const void* p) {
    uint32_t a;
    asm("{ .reg .u64 t; cvta.to.shared.u64 t, %1; cvt.u32.u64 %0, t; }"
        : "=r"(a) : "l"(p));
    return a;
}
__device__ __forceinline__ void cpasync16(uint32_t dst, const void* src) {
    asm volatile("cp.async.cg.shared.global [%0], [%1], 16;" :: "r"(dst), "l"(src));
}
__device__ __forceinline__ void cp_commit() {
    asm volatile("cp.async.commit_group;" ::: "memory");
}
template <int N> __device__ __forceinline__ void cp_wait() {
    asm volatile("cp.async.wait_group %0;" :: "n"(N) : "memory");
}
__device__ __forceinline__ void ldsm4(uint32_t* r, uint32_t addr) {
    asm volatile("ldmatrix.sync.aligned.m8n8.x4.shared.b16 {%0,%1,%2,%3}, [%4];"
                 : "=r"(r[0]), "=r"(r[1]), "=r"(r[2]), "=r"(r[3]) : "r"(addr));
}
__device__ __forceinline__ void mma16816(float* c, const uint32_t* a, const uint32_t* b) {
    asm volatile(
        "mma.sync.aligned.m16n8k16.row.col.f32.bf16.bf16.f32 "
        "{%0,%1,%2,%3}, {%4,%5,%6,%7}, {%8,%9}, {%0,%1,%2,%3};"
        : "+f"(c[0]), "+f"(c[1]), "+f"(c[2]), "+f"(c[3])
        : "r"(a[0]), "r"(a[1]), "r"(a[2]), "r"(a[3]), "r"(b[0]), "r"(b[1]));
}
__device__ __forceinline__ __nv_bfloat162 split_hi2(float x, float y) {
    __nv_bfloat162 h;
    h.x = __float2bfloat16(x); h.y = __float2bfloat16(y);
    return h;
}
__device__ __forceinline__ __nv_bfloat162 split_lo2(float x, float y, __nv_bfloat162 h) {
    __nv_bfloat162 l;
    l.x = __float2bfloat16(x - __bfloat162float(h.x));
    l.y = __float2bfloat16(y - __bfloat162float(h.y));
    return l;
}

// ---------------------------------------------------------------------------
// Split-precision bf16 GEMM on mma.sync.
// acc = alpha * (Ah*Bh^T + Ah*Bl^T + Al*Bh^T) (+ D), fp32 accum in regs.
// Tile 128x128, KC=32, 2-stage cp.async pipeline, 80B padded rows,
// 2 CTAs/SM (__launch_bounds__(256,2)), phased fragment loading.
// mode 0: outputs Cf (fp32) and/or Ch/Cl (bf16 hi/lo).
// mode 1 (fused QKV): segment col0>>11: 0->Ch/Cl (Q), 1->C2h/C2l (K), 2->Cf (V).
// ---------------------------------------------------------------------------
#define KC       32
#define ROW_B    80                        // 64B data + 16B pad (16B aligned)
#define TILE_PB  (128 * ROW_B)             // 10240
#define OFF_AH   0
#define OFF_AL   TILE_PB
#define OFF_BH   (2 * TILE_PB)
#define OFF_BL   (3 * TILE_PB)
#define STAGE_B  (4 * TILE_PB)             // 40960
#define NSTAGE   2
#define SMEM_DYN (NSTAGE * STAGE_B)        // 81920 -> 2 CTAs/SM

__global__ __launch_bounds__(256, 2)
void mma_gemm(const __nv_bfloat16* __restrict__ Ah, const __nv_bfloat16* __restrict__ Al,
              int lda, long sAo, long sAi,
              const __nv_bfloat16* __restrict__ Bh, const __nv_bfloat16* __restrict__ Bl,
              int ldb, long sBo, long sBi,
              float* __restrict__ Cf,
              __nv_bfloat16* __restrict__ Ch, __nv_bfloat16* __restrict__ Cl,
              __nv_bfloat16* __restrict__ C2h, __nv_bfloat16* __restrict__ C2l,
              int ldc, long sCo, long sCi,
              const float* __restrict__ D,
              int K, int inner, float alpha, int mode)
{
    extern __shared__ __align__(128) char dsm_raw[];
    const uint32_t dsm0 = smem_u32(dsm_raw);

    const int tid  = threadIdx.x;
    const int lane = tid & 31;
    const int wid  = tid >> 5;
    const int wm   = wid & 1;             // warp row (2): 64 rows
    const int wn   = wid >> 1;            // warp col (4): 32 cols

    const int z  = blockIdx.z;
    const int zo = z / inner, zi = z - zo * inner;
    Ah += zo * sAo + zi * sAi;  Al += zo * sAo + zi * sAi;
    Bh += zo * sBo + zi * sBi;  Bl += zo * sBo + zi * sBi;
    const long coff = zo * sCo + zi * sCi;

    // grouped rasterization: 8 M-tiles per stripe
    int pid_m, pid_n;
    {
        const int ntm = gridDim.y, ntn = gridDim.x;
        const int lin = blockIdx.y * ntn + blockIdx.x;
        const int G = 8;
        const int width = G * ntn;
        const int grp = lin / width;
        const int rem = lin - grp * width;
        const int m0  = grp * G;
        const int gsz = (ntm - m0 < G) ? (ntm - m0) : G;
        pid_m = m0 + rem % gsz;
        pid_n = rem / gsz;
    }
    const int row0 = pid_m * 128;
    const int col0 = pid_n * 128;

    // cp.async geometry: 512 16B-chunks per tile; 2 per thread per tile
    const int nk = K / KC;
    int rr[2], cc[2];
    #pragma unroll
    for (int j = 0; j < 2; j++) {
        int idx = tid + j * 256;
        rr[j] = idx >> 2;
        cc[j] = idx & 3;
    }

    auto load_stage = [&](int s, int k0) {
        const uint32_t sb = dsm0 + s * STAGE_B;
        #pragma unroll
        for (int j = 0; j < 2; j++) {
            const uint32_t so = (uint32_t)(rr[j] * ROW_B + cc[j] * 16);
            const long ga = (long)(row0 + rr[j]) * lda + k0 + cc[j] * 8;
            const long gb = (long)(col0 + rr[j]) * ldb + k0 + cc[j] * 8;
            cpasync16(sb + OFF_AH + so, Ah + ga);
            cpasync16(sb + OFF_AL + so, Al + ga);
            cpasync16(sb + OFF_BH + so, Bh + gb);
            cpasync16(sb + OFF_BL + so, Bl + gb);
        }
        cp_commit();
    };

    // ldsm lane geometry (80B rows; 8-row groups hit distinct 16B banks)
    const int l7 = lane & 7;
    const uint32_t aLd = (uint32_t)((wm * 64 + l7 + ((lane >> 3) & 1) * 8) * ROW_B
                                    + ((lane >> 4) & 1) * 16);
    const uint32_t bLd = (uint32_t)((wn * 32 + ((lane >> 4) & 1) * 8 + l7) * ROW_B
                                    + ((lane >> 3) & 1) * 16);

    float acc[4][4][4];
    #pragma unroll
    for (int mt = 0; mt < 4; mt++)
        #pragma unroll
        for (int nt = 0; nt < 4; nt++)
            #pragma unroll
            for (int q = 0; q < 4; q++) acc[mt][nt][q] = 0.f;

    load_stage(0, 0);
    load_stage(1, KC);

    for (int i = 0; i < nk; ++i) {
        const int s = i & 1;
        if (i + 1 < nk) cp_wait<1>(); else cp_wait<0>();
        __syncthreads();

        const uint32_t sb = dsm0 + s * STAGE_B;
        #pragma unroll
        for (int ks = 0; ks < 2; ++ks) {
            const uint32_t kOff = (uint32_t)(ks * 32);
            uint32_t fa[4][4], bh[4][2], bl[4][2];
            // phase 1: A-hi x (B-hi, B-lo)
            #pragma unroll
            for (int mt = 0; mt < 4; mt++)
                ldsm4(fa[mt], sb + OFF_AH + aLd + mt * (16 * ROW_B) + kOff);
            #pragma unroll
            for (int p = 0; p < 2; p++) {
                const uint32_t bd = sb + bLd + p * (16 * ROW_B) + kOff;
                ldsm4(&bh[2 * p][0], bd + OFF_BH);
                ldsm4(&bl[2 * p][0], bd + OFF_BL);
            }
            #pragma unroll
            for (int mt = 0; mt < 4; mt++)
                #pragma unroll
                for (int nt = 0; nt < 4; nt++) {
                    mma16816(acc[mt][nt], fa[mt], bh[nt]);
                    mma16816(acc[mt][nt], fa[mt], bl[nt]);
                }
            // phase 2: A-lo x B-hi (reuse fa registers)
            #pragma unroll
            for (int mt = 0; mt < 4; mt++)
                ldsm4(fa[mt], sb + OFF_AL + aLd + mt * (16 * ROW_B) + kOff);
            #pragma unroll
            for (int mt = 0; mt < 4; mt++)
                #pragma unroll
                for (int nt = 0; nt < 4; nt++)
                    mma16816(acc[mt][nt], fa[mt], bh[nt]);
        }
        __syncthreads();
        if (i + 2 < nk) load_stage(s, (i + 2) * KC);
    }

    // ---- epilogue
    float* cf = Cf;
    __nv_bfloat16 *ch = Ch, *cl = Cl;
    int cbase = col0;
    if (mode) {
        const int seg = col0 >> 11;
        cbase = col0 & 2047;
        if (seg == 0)      { cf = nullptr; ch = Ch;  cl = Cl;  }
        else if (seg == 1) { cf = nullptr; ch = C2h; cl = C2l; }
        else               { ch = nullptr; cl = nullptr; }
    }
    if (cf) cf += coff;
    if (ch) { ch += coff; cl += coff; }
    const float* dp = D ? (D + coff) : (const float*)0;

    const int cg = lane >> 2, tg = lane & 3;
    #pragma unroll
    for (int mt = 0; mt < 4; mt++) {
        #pragma unroll
        for (int nt = 0; nt < 4; nt++) {
            const int r = row0 + wm * 64 + mt * 16 + cg;
            const int c = cbase + wn * 32 + nt * 8 + tg * 2;
            const long o0 = (long)r * ldc + c;
            const long o1 = (long)(r + 8) * ldc + c;
            float2 v0, v1;
            v0.x = acc[mt][nt][0] * alpha; v0.y = acc[mt][nt][1] * alpha;
            v1.x = acc[mt][nt][2] * alpha; v1.y = acc[mt][nt][3] * alpha;
            if (dp) {
                float2 d0 = *(const float2*)(dp + o0);
                float2 d1 = *(const float2*)(dp + o1);
                v0.x += d0.x; v0.y += d0.y; v1.x += d1.x; v1.y += d1.y;
            }
            if (cf) {
                *(float2*)(cf + o0) = v0;
                *(float2*)(cf + o1) = v1;
            }
            if (ch) {
                __nv_bfloat162 h0 = split_hi2(v0.x, v0.y);
                __nv_bfloat162 h1 = split_hi2(v1.x, v1.y);
                *(__nv_bfloat162*)(ch + o0) = h0;
                *(__nv_bfloat162*)(ch + o1) = h1;
                *(__nv_bfloat162*)(cl + o0) = split_lo2(v0.x, v0.y, h0);
                *(__nv_bfloat162*)(cl + o1) = split_lo2(v1.x, v1.y, h1);
            }
        }
    }
}

// ---------------------------------------------------------------------------
// fp32 [R,C] -> bf16 hi/lo transposed [C,R]  (batched via strides)
// ---------------------------------------------------------------------------
__global__ void tsplit_kernel(const float* __restrict__ in, long sIo, long sIi, int ldin,
                              __nv_bfloat16* __restrict__ hi, __nv_bfloat16* __restrict__ lo,
                              long sOo, long sOi, int ldo, int inner)
{
    __shared__ float tile[32][33];
    const int z = blockIdx.z, zo = z / inner, zi = z - zo * inner;
    in += zo * sIo + zi * sIi;
    hi += zo * sOo + zi * sOi;
    lo += zo * sOo + zi * sOi;
    const int r0 = blockIdx.y * 32, c0 = blockIdx.x * 32;
    const int tx = threadIdx.x, ty = threadIdx.y;
    #pragma unroll
    for (int i = 0; i < 4; i++)
        tile[ty + i * 8][tx] = in[(long)(r0 + ty + i * 8) * ldin + c0 + tx];
    __syncthreads();
    const int t  = ty * 32 + tx;
    const int rp = t & 15;
    const int cb = t >> 4;
    #pragma unroll
    for (int pass = 0; pass < 2; pass++) {
        const int cl_ = cb + pass * 16;
        const float v0 = tile[2 * rp][cl_];
        const float v1 = tile[2 * rp + 1][cl_];
        __nv_bfloat162 h = split_hi2(v0, v1);
        const long o = (long)(c0 + cl_) * ldo + r0 + 2 * rp;
        *(__nv_bfloat162*)(hi + o) = h;
        *(__nv_bfloat162*)(lo + o) = split_lo2(v0, v1, h);
    }
}

// ---------------------------------------------------------------------------
// build X (gather + transpose + PE) writing fp32 AND bf16 hi/lo
// ---------------------------------------------------------------------------
__global__ void build_x_kernel(const float* __restrict__ ref,
                               const float* __restrict__ hd,
                               float* __restrict__ X,
                               __nv_bfloat16* __restrict__ Xh,
                               __nv_bfloat16* __restrict__ Xl)
{
    __shared__ float tile[32][33];
    const int b  = blockIdx.z;
    const int f0 = blockIdx.x * 32;
    const int t0 = blockIdx.y * 32;
    const int tx = threadIdx.x, ty = threadIdx.y;

#pragma unroll
    for (int i = 0; i < 4; i++) {
        int f  = f0 + ty + i * 8;
        int n_ = f >> 10;
        int s  = f & 1023;
        int hh = s >> 5;
        int ww = s & 31;
        const float* src = (ww < 16)
            ? ref + ((long)(((b * 8 + n_) * 32 + hh) * 16 + ww)) * 1024
            : hd  + ((long)(((b * 8 + n_) * 32 + hh) * 16 + (ww - 16))) * 1024;
        tile[ty + i * 8][tx] = src[t0 + tx];
    }
    __syncthreads();
#pragma unroll
    for (int i = 0; i < 4; i++) {
        int t = t0 + ty + i * 8;
        int f = f0 + tx;
        float freq = __expf((float)f * (-9.210340371976184f / 4096.0f));
        float ang  = (float)t * freq;
        float pe   = (f & 1) ? cosf(ang) : sinf(ang);
        float v    = tile[tx][ty + i * 8] + 0.001f * pe;
        long  o    = (long)b * PLANE + (long)t * DEMB + f;
        X[o] = v;
        __nv_bfloat16 h = __float2bfloat16(v);
        Xh[o] = h;
        Xl[o] = __float2bfloat16(v - __bfloat162float(h));
    }
}

// ---------------------------------------------------------------------------
// Softmax over rows of S, writing bf16 hi/lo P directly.
// ---------------------------------------------------------------------------
__global__ void softmax_kernel(const float* __restrict__ S,
                               __nv_bfloat16* __restrict__ Ph,
                               __nv_bfloat16* __restrict__ Pl)
{
    __shared__ float red[8];
    const int tid  = threadIdx.x;
    const int lane = tid & 31, warp = tid >> 5;
    const float4* row = (const float4*)(S + (long)blockIdx.x * SEQ);
    float4 v = row[tid];

    float m = fmaxf(fmaxf(v.x, v.y), fmaxf(v.z, v.w));
#pragma unroll
    for (int o = 16; o; o >>= 1) m = fmaxf(m, __shfl_xor_sync(~0u, m, o));
    if (lane == 0) red[warp] = m;
    __syncthreads();
    float M = red[0];
#pragma unroll
    for (int i = 1; i < 8; i++) M = fmaxf(M, red[i]);

    v.x = __expf(v.x - M); v.y = __expf(v.y - M);
    v.z = __expf(v.z - M); v.w = __expf(v.w - M);
    float s = v.x + v.y + v.z + v.w;
#pragma unroll
    for (int o = 16; o; o >>= 1) s += __shfl_xor_sync(~0u, s, o);
    __syncthreads();
    if (lane == 0) red[warp] = s;
    __syncthreads();
    float T = 0.f;
#pragma unroll
    for (int i = 0; i < 8; i++) T += red[i];
    float inv = 1.0f / T;
    v.x *= inv; v.y *= inv; v.z *= inv; v.w *= inv;

    const long o = (long)blockIdx.x * SEQ + tid * 4;
    __nv_bfloat162 h0 = split_hi2(v.x, v.y);
    __nv_bfloat162 h1 = split_hi2(v.z, v.w);
    *(__nv_bfloat162*)(Ph + o)     = h0;
    *(__nv_bfloat162*)(Ph + o + 2) = h1;
    *(__nv_bfloat162*)(Pl + o)     = split_lo2(v.x, v.y, h0);
    *(__nv_bfloat162*)(Pl + o + 2) = split_lo2(v.z, v.w, h1);
}

// ---------------------------------------------------------------------------
// LayerNorm statistics + output
// ---------------------------------------------------------------------------
__global__ void reduce_partial_kernel(const float* __restrict__ O,
                                      double* __restrict__ part)
{
    __shared__ double sh[256], sh2[256];
    const int b   = blockIdx.y;
    const int tid = threadIdx.x;
    const float* p = O + (long)b * PLANE;
    const int base = blockIdx.x * 256 + tid;
    double s = 0.0, s2 = 0.0;
#pragma unroll
    for (int i = 0; i < 32; i++) {
        float v = p[base + i * 262144];
        s  += v;
        s2 += (double)v * v;
    }
    sh[tid] = s; sh2[tid] = s2;
    __syncthreads();
    for (int o = 128; o; o >>= 1) {
        if (tid < o) { sh[tid] += sh[tid + o]; sh2[tid] += sh2[tid + o]; }
        __syncthreads();
    }
    if (tid == 0) {
        part[(b * 1024 + blockIdx.x) * 2 + 0] = sh[0];
        part[(b * 1024 + blockIdx.x) * 2 + 1] = sh2[0];
    }
}

__global__ void finalize_stats_kernel(const double* __restrict__ part)
{
    __shared__ double sh[256], sh2[256];
    const int b = blockIdx.x, tid = threadIdx.x;
    double s = 0.0, s2 = 0.0;
    for (int i = tid; i < 1024; i += 256) {
        s  += part[(b * 1024 + i) * 2 + 0];
        s2 += part[(b * 1024 + i) * 2 + 1];
    }
    sh[tid] = s; sh2[tid] = s2;
    __syncthreads();
    for (int o = 128; o; o >>= 1) {
        if (tid < o) { sh[tid] += sh[tid + o]; sh2[tid] += sh2[tid + o]; }
        __syncthreads();
    }
    if (tid == 0) {
        double n    = (double)PLANE;
        double mean = sh[0] / n;
        double var  = sh2[0] / n - mean * mean;
        g_mean[b] = mean;
        g_rstd[b] = rsqrt(var + 1e-6);
    }
}

__global__ void ln_out_kernel(const float* __restrict__ O,
                              const float* __restrict__ gamma,
                              const float* __restrict__ beta,
                              float* __restrict__ out)
{
    __shared__ float tile[32][33];
    const int bz = blockIdx.z;
    const int b  = bz >> 3;
    const int nf = (bz & 7) * 1024;
    const int c0 = blockIdx.x * 32;
    const int t0 = blockIdx.y * 32;
    const int tx = threadIdx.x, ty = threadIdx.y;
    const float mean = (float)g_mean[b];
    const float rstd = (float)g_rstd[b];

#pragma unroll
    for (int i = 0; i < 4; i++) {
        int t   = t0 + ty + i * 8;
        long fi = (long)t * DEMB + nf + c0 + tx;
        float v = O[(long)b * PLANE + fi];
        tile[ty + i * 8][tx] = (v - mean) * rstd * gamma[fi] + beta[fi];
    }
    __syncthreads();
#pragma unroll
    for (int i = 0; i < 4; i++) {
        int c = c0 + ty + i * 8;
        out[((long)bz * 1024 + c) * 1024 + t0 + tx] = tile[tx][ty + i * 8];
    }
}

// ---------------------------------------------------------------------------
// Launcher
// ---------------------------------------------------------------------------
extern "C" void kernel_launch(void* const* d_in, const int* in_sizes, int n_in,
                              void* d_out, int out_size)
{
    const float* ref_img = (const float*)d_in[0];
    const float* hdmap   = (const float*)d_in[1];
    const float* w_q     = (const float*)d_in[2];
    const float* w_k     = (const float*)d_in[3];
    const float* w_v     = (const float*)d_in[4];
    const float* w_o     = (const float*)d_in[5];
    const float* gamma   = (const float*)d_in[6];
    const float* beta    = (const float*)d_in[7];
    float* out = (float*)d_out;

    float *X, *V, *S, *O;  double* part;
    __nv_bfloat16 *Xh, *Xl, *Wqkvth, *Wqkvtl, *Woth, *Wotl;
    __nv_bfloat16 *Qh, *Ql, *Kh, *Kl, *Vth, *Vtl, *Ph, *Pl, *Zh, *Zl;
    cudaGetSymbolAddress((void**)&X, g_X);     cudaGetSymbolAddress((void**)&V, g_V);
    cudaGetSymbolAddress((void**)&S, g_S);     cudaGetSymbolAddress((void**)&O, g_O);
    cudaGetSymbolAddress((void**)&part, g_part);
    cudaGetSymbolAddress((void**)&Xh, g_Xh);   cudaGetSymbolAddress((void**)&Xl, g_Xl);
    cudaGetSymbolAddress((void**)&Wqkvth, g_Wqkvth);
    cudaGetSymbolAddress((void**)&Wqkvtl, g_Wqkvtl);
    cudaGetSymbolAddress((void**)&Woth, g_Woth); cudaGetSymbolAddress((void**)&Wotl, g_Wotl);
    cudaGetSymbolAddress((void**)&Qh, g_Qh);   cudaGetSymbolAddress((void**)&Ql, g_Ql);
    cudaGetSymbolAddress((void**)&Kh, g_Kh);   cudaGetSymbolAddress((void**)&Kl, g_Kl);
    cudaGetSymbolAddress((void**)&Vth, g_Vth); cudaGetSymbolAddress((void**)&Vtl, g_Vtl);
    cudaGetSymbolAddress((void**)&Ph, g_Ph);   cudaGetSymbolAddress((void**)&Pl, g_Pl);
    cudaGetSymbolAddress((void**)&Zh, g_Zh);   cudaGetSymbolAddress((void**)&Zl, g_Zl);

    cudaFuncSetAttribute(mma_gemm, cudaFuncAttributeMaxDynamicSharedMemorySize, SMEM_DYN);

    const dim3 tb32x8(32, 8);

    // 1) build X (gather + transpose + PE) with fused hi/lo split
    build_x_kernel<<<dim3(DEMB / 32, SEQ / 32, BATCH), tb32x8>>>(ref_img, hdmap, X, Xh, Xl);

    // 2) weight transpose + split: w_q/k/v -> rows of Wqkvt [6144, 8192]; w_o -> Wot
    tsplit_kernel<<<dim3(QKVDIM / 32, DEMB / 32, 1), tb32x8>>>(
        w_q, 0, 0, QKVDIM, Wqkvth, Wqkvtl, 0, 0, DEMB, 1);
    tsplit_kernel<<<dim3(QKVDIM / 32, DEMB / 32, 1), tb32x8>>>(
        w_k, 0, 0, QKVDIM, Wqkvth + (long)QKVDIM * DEMB, Wqkvtl + (long)QKVDIM * DEMB, 0, 0, DEMB, 1);
    tsplit_kernel<<<dim3(QKVDIM / 32, DEMB / 32, 1), tb32x8>>>(
        w_v, 0, 0, QKVDIM, Wqkvth + (long)2 * QKVDIM * DEMB, Wqkvtl + (long)2 * QKVDIM * DEMB, 0, 0, DEMB, 1);
    tsplit_kernel<<<dim3(DEMB / 32, QKVDIM / 32, 1), tb32x8>>>(
        w_o, 0, 0, DEMB, Woth, Wotl, 0, 0, QKVDIM, 1);

    // 3) fused QKV projection: [4096,8192] x [8192,6144]
    mma_gemm<<<dim3(3 * QKVDIM / 128, TOK_TOTAL / 128, 1), 256, SMEM_DYN>>>(
        Xh, Xl, DEMB, 0, 0,
        Wqkvth, Wqkvtl, DEMB, 0, 0,
        V, Qh, Ql, Kh, Kl, QKVDIM, 0, 0,
        nullptr, DEMB, 1, 1.0f, 1);

    // 4) transpose+split V per head -> Vt[b,h,d,t]
    tsplit_kernel<<<dim3(DKV / 32, SEQ / 32, BATCH * NHEAD), tb32x8>>>(
        V, (long)SEQ * QKVDIM, DKV, QKVDIM,
        Vth, Vtl, (long)NHEAD * DKV * SEQ, (long)DKV * SEQ, SEQ, NHEAD);

    // 5) scores S = (1/16) Q K^T per (b,h)
    const long sQKo = (long)SEQ * QKVDIM;
    const long sSo  = (long)NHEAD * SEQ * SEQ;
    mma_gemm<<<dim3(SEQ / 128, SEQ / 128, BATCH * NHEAD), 256, SMEM_DYN>>>(
        Qh, Ql, QKVDIM, sQKo, DKV,
        Kh, Kl, QKVDIM, sQKo, DKV,
        S, nullptr, nullptr, nullptr, nullptr, SEQ, sSo, (long)SEQ * SEQ,
        nullptr, DKV, NHEAD, 0.0625f, 0);

    // 6) softmax with fused P split
    softmax_kernel<<<BATCH * NHEAD * SEQ, 256>>>(S, Ph, Pl);

    // 7) Z = P @ V per (b,h)
    mma_gemm<<<dim3(DKV / 128, SEQ / 128, BATCH * NHEAD), 256, SMEM_DYN>>>(
        Ph, Pl, SEQ, sSo, (long)SEQ * SEQ,
        Vth, Vtl, SEQ, (long)NHEAD * DKV * SEQ, (long)DKV * SEQ,
        nullptr, Zh, Zl, nullptr, nullptr, QKVDIM, sQKo, DKV,
        nullptr, SEQ, NHEAD, 1.0f, 0);

    // 8) O = Z @ w_o + X (residual)
    mma_gemm<<<dim3(DEMB / 128, TOK_TOTAL / 128, 1), 256, SMEM_DYN>>>(
        Zh, Zl, QKVDIM, 0, 0, Woth, Wotl, QKVDIM, 0, 0,
        O, nullptr, nullptr, nullptr, nullptr, DEMB, 0, 0,
        X, QKVDIM, 1, 1.0f, 0);

    // 9) LayerNorm stats + normalize/transpose out
    reduce_partial_kernel<<<dim3(1024, BATCH), 256>>>(O, part);
    finalize_stats_kernel<<<BATCH, 256>>>(part);
    ln_out_kernel<<<dim3(32, 32, BATCH * NHEAD), tb32x8>>>(O, gamma, beta, out);
}